// round 15
// baseline (speedup 1.0000x reference)
#include <cuda_runtime.h>
#include <cuda_bf16.h>
#include <cstdint>

#define S_GRID 14
#define INV_S (1.0f / 14.0f)
#define L_COORD 5.0f
#define L_NOOBJ 0.5f
#define TPB 128                  // threads per block
#define WARPS 4                  // warps per block
#define WTILE 32                 // cells per warp-tile
#define TILE_F (WTILE * 30)      // 960 floats per tile
#define TILE_BYTES (TILE_F * 4)  // 3840 bytes per tile
#define STAGES 3                 // per-warp ring depth

// Accumulators: [0]=reg, [1]=contain, [2]=noobj, [3]=cls
__device__ float g_acc[4];
__device__ unsigned int g_block_count;

__device__ __forceinline__ uint32_t smem_u32(const void* p) {
    return (uint32_t)__cvta_generic_to_shared(p);
}
__device__ __forceinline__ void mbar_init(uint32_t mbar, uint32_t count) {
    asm volatile("mbarrier.init.shared.b64 [%0], %1;" :: "r"(mbar), "r"(count) : "memory");
}
__device__ __forceinline__ void mbar_expect_tx(uint32_t mbar, uint32_t bytes) {
    asm volatile("mbarrier.arrive.expect_tx.shared.b64 _, [%0], %1;"
                 :: "r"(mbar), "r"(bytes) : "memory");
}
// 1D bulk TMA: global -> shared, completion via mbarrier complete_tx.
__device__ __forceinline__ void tma_bulk_g2s(uint32_t dst, const void* src,
                                             uint32_t bytes, uint32_t mbar) {
    asm volatile(
        "cp.async.bulk.shared::cluster.global.mbarrier::complete_tx::bytes "
        "[%0], [%1], %2, [%3];"
        :: "r"(dst), "l"(src), "r"(bytes), "r"(mbar) : "memory");
}
__device__ __forceinline__ void mbar_wait(uint32_t mbar, uint32_t parity) {
    uint32_t done;
    asm volatile(
        "{\n\t.reg .pred p;\n\t"
        "mbarrier.try_wait.parity.acquire.cta.shared::cta.b64 p, [%1], %2;\n\t"
        "selp.b32 %0, 1, 0, p;\n\t}"
        : "=r"(done) : "r"(mbar), "r"(parity) : "memory");
    while (!done) {
        asm volatile(
            "{\n\t.reg .pred p;\n\t"
            "mbarrier.try_wait.parity.acquire.cta.shared::cta.b64 p, [%1], %2, 0x989680;\n\t"
            "selp.b32 %0, 1, 0, p;\n\t}"
            : "=r"(done) : "r"(mbar), "r"(parity) : "memory");
    }
}

__device__ __forceinline__ float iou_vs_tgt(float x, float y, float w, float h,
                                            float tx1, float ty1, float tx2, float ty2,
                                            float ta) {
    float cx = x * INV_S;
    float cy = y * INV_S;
    float x1 = cx - 0.5f * w, y1 = cy - 0.5f * h;
    float x2 = cx + 0.5f * w, y2 = cy + 0.5f * h;
    float lx = fmaxf(x1, tx1), ly = fmaxf(y1, ty1);
    float rx = fminf(x2, tx2), ry = fminf(y2, ty2);
    float iw = fmaxf(rx - lx, 0.0f), ih = fmaxf(ry - ly, 0.0f);
    float inter = iw * ih;
    float a1 = (x2 - x1) * (y2 - y1);
    return inter / (a1 + ta - inter);
}

__global__ void __launch_bounds__(TPB, 4) yolo_tma_kernel(
    const float* __restrict__ pred,            // [ncells, 30]
    const float* __restrict__ tbox,            // [ncells, 4]
    const float* __restrict__ tcls,            // [ncells, 20]
    const unsigned int* __restrict__ objmap,   // [ncells] bool widened to 4B
    float* __restrict__ out,
    int ncells, int ntiles_full, int nwarps_total, float inv_n) {

    __shared__ __align__(16) float s_pred[WARPS][STAGES][TILE_F];   // 46 KB
    __shared__ __align__(8) unsigned long long s_mbar[WARPS][STAGES];
    __shared__ float s_red[WARPS][4];
    __shared__ bool s_is_last;

    int tid  = threadIdx.x;
    int lane = tid & 31;
    int warp = tid >> 5;
    int gwarp = blockIdx.x * WARPS + warp;

    // Init this block's mbarriers (arrive count = 1: the elect-lane expect_tx)
    if (tid < WARPS * STAGES)
        mbar_init(smem_u32(&s_mbar[tid / STAGES][tid % STAGES]), 1);
    __syncthreads();

    uint32_t mb_base  = smem_u32(&s_mbar[warp][0]);
    uint32_t buf_base = smem_u32(&s_pred[warp][0][0]);

    float reg = 0.0f, contain = 0.0f, noobj = 0.0f, cls = 0.0f;

    int tile = gwarp;
    int stride = nwarps_total;
    int st = 0, round = 0;

    if (tile < ntiles_full) {
        // Prologue: prefetch tiles n=0 and n=1 of this warp's sequence.
        if (lane == 0) {
            mbar_expect_tx(mb_base, TILE_BYTES);
            tma_bulk_g2s(buf_base, pred + (size_t)tile * TILE_F, TILE_BYTES, mb_base);
            if (tile + stride < ntiles_full) {
                mbar_expect_tx(mb_base + 8, TILE_BYTES);
                tma_bulk_g2s(buf_base + TILE_BYTES,
                             pred + (size_t)(tile + stride) * TILE_F, TILE_BYTES,
                             mb_base + 8);
            }
        }

        for (; tile < ntiles_full; tile += stride) {
            int i = tile * WTILE + lane;
            unsigned int flag = objmap[i];
            bool has_obj = (flag != 0u);

            // Hoisted obj-path gathers: overlap TMA drain.
            float4 tb = make_float4(0.f, 0.f, 0.f, 0.f);
            float4 tcv[5];
            if (has_obj) {
                tb = __ldg(reinterpret_cast<const float4*>(tbox + (size_t)i * 4));
                const float4* tc4 = reinterpret_cast<const float4*>(tcls + (size_t)i * 20);
                #pragma unroll
                for (int j = 0; j < 5; j++) tcv[j] = __ldg(tc4 + j);
            }

            // Prefetch tile t+2*stride into stage (st+2)%STAGES.
            int next2 = tile + 2 * stride;
            if (lane == 0 && next2 < ntiles_full) {
                int s2 = st + 2; if (s2 >= STAGES) s2 -= STAGES;
                uint32_t mb2 = mb_base + (uint32_t)s2 * 8;
                mbar_expect_tx(mb2, TILE_BYTES);
                tma_bulk_g2s(buf_base + (uint32_t)s2 * TILE_BYTES,
                             pred + (size_t)next2 * TILE_F, TILE_BYTES, mb2);
            }

            // Wait for this tile's TMA completion (phase parity = round).
            mbar_wait(mb_base + (uint32_t)st * 8, (uint32_t)round);
            __syncwarp();

            const float* pv = &s_pred[warp][st][0] + lane * 30;

            if (!has_obj) {
                float c1 = pv[4], c2 = pv[9];
                noobj += L_NOOBJ * (c1 * c1 + c2 * c2);
            } else {
                float csum = 0.0f;
                #pragma unroll
                for (int j = 0; j < 5; j++) {
                    float d0 = pv[10 + 4 * j + 0] - tcv[j].x;
                    float d1 = pv[10 + 4 * j + 1] - tcv[j].y;
                    float d2 = pv[10 + 4 * j + 2] - tcv[j].z;
                    float d3 = pv[10 + 4 * j + 3] - tcv[j].w;
                    csum += d0 * d0 + d1 * d1 + d2 * d2 + d3 * d3;
                }
                cls += csum;

                float tcx = tb.x * INV_S, tcy = tb.y * INV_S;
                float tx1 = tcx - 0.5f * tb.z, ty1 = tcy - 0.5f * tb.w;
                float tx2 = tcx + 0.5f * tb.z, ty2 = tcy + 0.5f * tb.w;
                float ta = (tx2 - tx1) * (ty2 - ty1);

                float iou1 = iou_vs_tgt(pv[0], pv[1], pv[2], pv[3], tx1, ty1, tx2, ty2, ta);
                float iou2 = iou_vs_tgt(pv[5], pv[6], pv[7], pv[8], tx1, ty1, tx2, ty2, ta);

                bool take1 = iou1 > iou2;
                float best_iou = take1 ? iou1 : iou2;
                float bx = take1 ? pv[0] : pv[5];
                float by = take1 ? pv[1] : pv[6];
                float bw = take1 ? pv[2] : pv[7];
                float bh = take1 ? pv[3] : pv[8];
                float bc = take1 ? pv[4] : pv[9];

                float dx = bx - tb.x, dy = by - tb.y;
                float xy_err = dx * dx + dy * dy;
                float dw = sqrtf(bw) - sqrtf(tb.z);
                float dh = sqrtf(bh) - sqrtf(tb.w);
                float wh_err = dw * dw + dh * dh;
                reg += L_COORD * (xy_err + wh_err);

                float dc = bc - best_iou;
                contain += dc * dc;
            }
            __syncwarp();    // warp done with stage st before lane0 reuses it
            st++; if (st == STAGES) { st = 0; round ^= 1; }
        }
    }

    // Remainder cells (ncells % WTILE, normally 0): direct global processing.
    if (blockIdx.x == 0 && warp == 0) {
        for (int i = ntiles_full * WTILE + lane; i < ncells; i += 32) {
            unsigned int flag = objmap[i];
            const float* p = pred + (size_t)i * 30;
            if (flag == 0u) {
                float c1 = __ldg(p + 4), c2 = __ldg(p + 9);
                noobj += L_NOOBJ * (c1 * c1 + c2 * c2);
            } else {
                float pv[30];
                #pragma unroll
                for (int j = 0; j < 15; j++) {
                    float2 v = __ldg(reinterpret_cast<const float2*>(p + 2 * j));
                    pv[2 * j] = v.x; pv[2 * j + 1] = v.y;
                }
                float4 tb = __ldg(reinterpret_cast<const float4*>(tbox + (size_t)i * 4));
                const float4* tc4 = reinterpret_cast<const float4*>(tcls + (size_t)i * 20);
                float csum = 0.0f;
                #pragma unroll
                for (int j = 0; j < 5; j++) {
                    float4 t = __ldg(tc4 + j);
                    float d0 = pv[10 + 4 * j + 0] - t.x;
                    float d1 = pv[10 + 4 * j + 1] - t.y;
                    float d2 = pv[10 + 4 * j + 2] - t.z;
                    float d3 = pv[10 + 4 * j + 3] - t.w;
                    csum += d0 * d0 + d1 * d1 + d2 * d2 + d3 * d3;
                }
                cls += csum;
                float tcx = tb.x * INV_S, tcy = tb.y * INV_S;
                float tx1 = tcx - 0.5f * tb.z, ty1 = tcy - 0.5f * tb.w;
                float tx2 = tcx + 0.5f * tb.z, ty2 = tcy + 0.5f * tb.w;
                float ta = (tx2 - tx1) * (ty2 - ty1);
                float iou1 = iou_vs_tgt(pv[0], pv[1], pv[2], pv[3], tx1, ty1, tx2, ty2, ta);
                float iou2 = iou_vs_tgt(pv[5], pv[6], pv[7], pv[8], tx1, ty1, tx2, ty2, ta);
                bool take1 = iou1 > iou2;
                float best_iou = take1 ? iou1 : iou2;
                float bx = take1 ? pv[0] : pv[5];
                float by = take1 ? pv[1] : pv[6];
                float bw = take1 ? pv[2] : pv[7];
                float bh = take1 ? pv[3] : pv[8];
                float bc = take1 ? pv[4] : pv[9];
                float dx = bx - tb.x, dy = by - tb.y;
                float dwv = sqrtf(bw) - sqrtf(tb.z);
                float dhv = sqrtf(bh) - sqrtf(tb.w);
                reg += L_COORD * (dx * dx + dy * dy + dwv * dwv + dhv * dhv);
                float dc = bc - best_iou;
                contain += dc * dc;
            }
        }
    }

    // ---- One reduction per block (4 warps) ----
    #pragma unroll
    for (int off = 16; off > 0; off >>= 1) {
        reg     += __shfl_down_sync(0xFFFFFFFFu, reg, off);
        contain += __shfl_down_sync(0xFFFFFFFFu, contain, off);
        noobj   += __shfl_down_sync(0xFFFFFFFFu, noobj, off);
        cls     += __shfl_down_sync(0xFFFFFFFFu, cls, off);
    }

    if (lane == 0) {
        s_red[warp][0] = reg;
        s_red[warp][1] = contain;
        s_red[warp][2] = noobj;
        s_red[warp][3] = cls;
    }
    __syncthreads();

    if (warp == 0) {
        int comp = lane >> 2;     // 0..3 (lanes 0..15)
        int w    = lane & 3;      // 0..3
        float v = (lane < 16) ? s_red[w][comp] : 0.0f;
        v += __shfl_down_sync(0xFFFFFFFFu, v, 2);
        v += __shfl_down_sync(0xFFFFFFFFu, v, 1);
        if (lane < 16 && w == 0) atomicAdd(&g_acc[comp], v);
        __syncwarp();
        if (lane == 0) {
            __threadfence();
            unsigned int done = atomicAdd(&g_block_count, 1u);
            s_is_last = (done == gridDim.x - 1);
        }
    }
    __syncthreads();

    if (s_is_last && tid == 0) {
        float r  = g_acc[0];
        float ct = g_acc[1];
        float no = g_acc[2];
        float cl = g_acc[3];
        float total = r + ct + no + cl;
        out[0] = total * inv_n;
        out[1] = r  * inv_n;
        out[2] = ct * inv_n;
        out[3] = no * inv_n;
        out[4] = cl * inv_n;
        g_acc[0] = 0.0f; g_acc[1] = 0.0f; g_acc[2] = 0.0f; g_acc[3] = 0.0f;
        g_block_count = 0u;
        __threadfence();
    }
}

extern "C" void kernel_launch(void* const* d_in, const int* in_sizes, int n_in,
                              void* d_out, int out_size) {
    const float* pred = (const float*)d_in[0];
    const float* tbox = (const float*)d_in[1];
    const float* tcls = (const float*)d_in[2];
    const unsigned int* objmap = (const unsigned int*)d_in[3];

    int ncells = in_sizes[1] / 4;             // target_boxes has 4 per cell
    int n_imgs = ncells / (S_GRID * S_GRID);  // 4096
    int ntiles_full = ncells / WTILE;         // 25088 (exact)

    int dev = 0, sms = 148;
    cudaGetDevice(&dev);
    cudaDeviceGetAttribute(&sms, cudaDevAttrMultiProcessorCount, dev);
    int blocks = sms * 4;                     // 4 blocks/SM (46KB smem each)
    int max_blocks = (ntiles_full + WARPS - 1) / WARPS;
    if (blocks > max_blocks && max_blocks > 0) blocks = max_blocks;
    if (blocks < 1) blocks = 1;
    int nwarps_total = blocks * WARPS;

    yolo_tma_kernel<<<blocks, TPB>>>(pred, tbox, tcls, objmap,
                                     (float*)d_out, ncells, ntiles_full,
                                     nwarps_total, 1.0f / (float)n_imgs);
}

// round 16
// speedup vs baseline: 1.0084x; 1.0084x over previous
#include <cuda_runtime.h>
#include <cuda_bf16.h>
#include <cstdint>

#define S_GRID 14
#define INV_S (1.0f / 14.0f)
#define L_COORD 5.0f
#define L_NOOBJ 0.5f
#define TPB 128                  // threads per block
#define WARPS 4                  // warps per block
#define WTILE 32                 // cells per warp-tile
#define TILE_F (WTILE * 30)      // 960 floats per tile
#define TILE_BYTES (TILE_F * 4)  // 3840 bytes per tile
#define STAGES 3                 // per-warp ring depth

// Accumulators: [0]=reg, [1]=contain, [2]=noobj, [3]=cls
__device__ float g_acc[4];
__device__ unsigned int g_block_count;

__device__ __forceinline__ uint32_t smem_u32(const void* p) {
    return (uint32_t)__cvta_generic_to_shared(p);
}
__device__ __forceinline__ void mbar_init(uint32_t mbar, uint32_t count) {
    asm volatile("mbarrier.init.shared.b64 [%0], %1;" :: "r"(mbar), "r"(count) : "memory");
}
__device__ __forceinline__ void mbar_expect_tx(uint32_t mbar, uint32_t bytes) {
    asm volatile("mbarrier.arrive.expect_tx.shared.b64 _, [%0], %1;"
                 :: "r"(mbar), "r"(bytes) : "memory");
}
// 1D bulk TMA: global -> shared, completion via mbarrier complete_tx.
__device__ __forceinline__ void tma_bulk_g2s(uint32_t dst, const void* src,
                                             uint32_t bytes, uint32_t mbar) {
    asm volatile(
        "cp.async.bulk.shared::cluster.global.mbarrier::complete_tx::bytes "
        "[%0], [%1], %2, [%3];"
        :: "r"(dst), "l"(src), "r"(bytes), "r"(mbar) : "memory");
}
__device__ __forceinline__ void mbar_wait(uint32_t mbar, uint32_t parity) {
    uint32_t done;
    asm volatile(
        "{\n\t.reg .pred p;\n\t"
        "mbarrier.try_wait.parity.acquire.cta.shared::cta.b64 p, [%1], %2;\n\t"
        "selp.b32 %0, 1, 0, p;\n\t}"
        : "=r"(done) : "r"(mbar), "r"(parity) : "memory");
    while (!done) {
        asm volatile(
            "{\n\t.reg .pred p;\n\t"
            "mbarrier.try_wait.parity.acquire.cta.shared::cta.b64 p, [%1], %2, 0x989680;\n\t"
            "selp.b32 %0, 1, 0, p;\n\t}"
            : "=r"(done) : "r"(mbar), "r"(parity) : "memory");
    }
}

__device__ __forceinline__ float iou_vs_tgt(float x, float y, float w, float h,
                                            float tx1, float ty1, float tx2, float ty2,
                                            float ta) {
    float cx = x * INV_S;
    float cy = y * INV_S;
    float x1 = cx - 0.5f * w, y1 = cy - 0.5f * h;
    float x2 = cx + 0.5f * w, y2 = cy + 0.5f * h;
    float lx = fmaxf(x1, tx1), ly = fmaxf(y1, ty1);
    float rx = fminf(x2, tx2), ry = fminf(y2, ty2);
    float iw = fmaxf(rx - lx, 0.0f), ih = fmaxf(ry - ly, 0.0f);
    float inter = iw * ih;
    float a1 = (x2 - x1) * (y2 - y1);
    return inter / (a1 + ta - inter);
}

__global__ void __launch_bounds__(TPB, 4) yolo_tma_kernel(
    const float* __restrict__ pred,            // [ncells, 30]
    const float* __restrict__ tbox,            // [ncells, 4]
    const float* __restrict__ tcls,            // [ncells, 20]
    const unsigned int* __restrict__ objmap,   // [ncells] bool widened to 4B
    float* __restrict__ out,
    int ncells, int ntiles_full, int nwarps_total, float inv_n) {

    __shared__ __align__(16) float s_pred[WARPS][STAGES][TILE_F];   // 46 KB
    __shared__ __align__(8) unsigned long long s_mbar[WARPS][STAGES];
    __shared__ float s_red[WARPS][4];
    __shared__ bool s_is_last;

    int tid  = threadIdx.x;
    int lane = tid & 31;
    int warp = tid >> 5;
    int gwarp = blockIdx.x * WARPS + warp;

    // Init this block's mbarriers (arrive count = 1: the elect-lane expect_tx)
    if (tid < WARPS * STAGES)
        mbar_init(smem_u32(&s_mbar[tid / STAGES][tid % STAGES]), 1);
    __syncthreads();

    uint32_t mb_base  = smem_u32(&s_mbar[warp][0]);
    uint32_t buf_base = smem_u32(&s_pred[warp][0][0]);

    float reg = 0.0f, contain = 0.0f, noobj = 0.0f, cls = 0.0f;

    int tile = gwarp;
    int stride = nwarps_total;
    int st = 0, round = 0;

    if (tile < ntiles_full) {
        // Prologue: prefetch tiles n=0 and n=1 of this warp's sequence.
        if (lane == 0) {
            mbar_expect_tx(mb_base, TILE_BYTES);
            tma_bulk_g2s(buf_base, pred + (size_t)tile * TILE_F, TILE_BYTES, mb_base);
            if (tile + stride < ntiles_full) {
                mbar_expect_tx(mb_base + 8, TILE_BYTES);
                tma_bulk_g2s(buf_base + TILE_BYTES,
                             pred + (size_t)(tile + stride) * TILE_F, TILE_BYTES,
                             mb_base + 8);
            }
        }

        for (; tile < ntiles_full; tile += stride) {
            int i = tile * WTILE + lane;
            unsigned int flag = objmap[i];
            bool has_obj = (flag != 0u);

            // Hoisted obj-path gathers: overlap TMA drain.
            float4 tb = make_float4(0.f, 0.f, 0.f, 0.f);
            float4 tcv[5];
            if (has_obj) {
                tb = __ldg(reinterpret_cast<const float4*>(tbox + (size_t)i * 4));
                const float4* tc4 = reinterpret_cast<const float4*>(tcls + (size_t)i * 20);
                #pragma unroll
                for (int j = 0; j < 5; j++) tcv[j] = __ldg(tc4 + j);
            }

            // Prefetch tile t+2*stride into stage (st+2)%STAGES.
            int next2 = tile + 2 * stride;
            if (lane == 0 && next2 < ntiles_full) {
                int s2 = st + 2; if (s2 >= STAGES) s2 -= STAGES;
                uint32_t mb2 = mb_base + (uint32_t)s2 * 8;
                mbar_expect_tx(mb2, TILE_BYTES);
                tma_bulk_g2s(buf_base + (uint32_t)s2 * TILE_BYTES,
                             pred + (size_t)next2 * TILE_F, TILE_BYTES, mb2);
            }

            // Wait for this tile's TMA completion (phase parity = round).
            mbar_wait(mb_base + (uint32_t)st * 8, (uint32_t)round);
            __syncwarp();

            const float* pv = &s_pred[warp][st][0] + lane * 30;

            if (!has_obj) {
                float c1 = pv[4], c2 = pv[9];
                noobj += L_NOOBJ * (c1 * c1 + c2 * c2);
            } else {
                float csum = 0.0f;
                #pragma unroll
                for (int j = 0; j < 5; j++) {
                    float d0 = pv[10 + 4 * j + 0] - tcv[j].x;
                    float d1 = pv[10 + 4 * j + 1] - tcv[j].y;
                    float d2 = pv[10 + 4 * j + 2] - tcv[j].z;
                    float d3 = pv[10 + 4 * j + 3] - tcv[j].w;
                    csum += d0 * d0 + d1 * d1 + d2 * d2 + d3 * d3;
                }
                cls += csum;

                float tcx = tb.x * INV_S, tcy = tb.y * INV_S;
                float tx1 = tcx - 0.5f * tb.z, ty1 = tcy - 0.5f * tb.w;
                float tx2 = tcx + 0.5f * tb.z, ty2 = tcy + 0.5f * tb.w;
                float ta = (tx2 - tx1) * (ty2 - ty1);

                float iou1 = iou_vs_tgt(pv[0], pv[1], pv[2], pv[3], tx1, ty1, tx2, ty2, ta);
                float iou2 = iou_vs_tgt(pv[5], pv[6], pv[7], pv[8], tx1, ty1, tx2, ty2, ta);

                bool take1 = iou1 > iou2;
                float best_iou = take1 ? iou1 : iou2;
                float bx = take1 ? pv[0] : pv[5];
                float by = take1 ? pv[1] : pv[6];
                float bw = take1 ? pv[2] : pv[7];
                float bh = take1 ? pv[3] : pv[8];
                float bc = take1 ? pv[4] : pv[9];

                float dx = bx - tb.x, dy = by - tb.y;
                float xy_err = dx * dx + dy * dy;
                float dw = sqrtf(bw) - sqrtf(tb.z);
                float dh = sqrtf(bh) - sqrtf(tb.w);
                float wh_err = dw * dw + dh * dh;
                reg += L_COORD * (xy_err + wh_err);

                float dc = bc - best_iou;
                contain += dc * dc;
            }
            __syncwarp();    // warp done with stage st before lane0 reuses it
            st++; if (st == STAGES) { st = 0; round ^= 1; }
        }
    }

    // Remainder cells (ncells % WTILE, normally 0): direct global processing.
    if (blockIdx.x == 0 && warp == 0) {
        for (int i = ntiles_full * WTILE + lane; i < ncells; i += 32) {
            unsigned int flag = objmap[i];
            const float* p = pred + (size_t)i * 30;
            if (flag == 0u) {
                float c1 = __ldg(p + 4), c2 = __ldg(p + 9);
                noobj += L_NOOBJ * (c1 * c1 + c2 * c2);
            } else {
                float pv[30];
                #pragma unroll
                for (int j = 0; j < 15; j++) {
                    float2 v = __ldg(reinterpret_cast<const float2*>(p + 2 * j));
                    pv[2 * j] = v.x; pv[2 * j + 1] = v.y;
                }
                float4 tb = __ldg(reinterpret_cast<const float4*>(tbox + (size_t)i * 4));
                const float4* tc4 = reinterpret_cast<const float4*>(tcls + (size_t)i * 20);
                float csum = 0.0f;
                #pragma unroll
                for (int j = 0; j < 5; j++) {
                    float4 t = __ldg(tc4 + j);
                    float d0 = pv[10 + 4 * j + 0] - t.x;
                    float d1 = pv[10 + 4 * j + 1] - t.y;
                    float d2 = pv[10 + 4 * j + 2] - t.z;
                    float d3 = pv[10 + 4 * j + 3] - t.w;
                    csum += d0 * d0 + d1 * d1 + d2 * d2 + d3 * d3;
                }
                cls += csum;
                float tcx = tb.x * INV_S, tcy = tb.y * INV_S;
                float tx1 = tcx - 0.5f * tb.z, ty1 = tcy - 0.5f * tb.w;
                float tx2 = tcx + 0.5f * tb.z, ty2 = tcy + 0.5f * tb.w;
                float ta = (tx2 - tx1) * (ty2 - ty1);
                float iou1 = iou_vs_tgt(pv[0], pv[1], pv[2], pv[3], tx1, ty1, tx2, ty2, ta);
                float iou2 = iou_vs_tgt(pv[5], pv[6], pv[7], pv[8], tx1, ty1, tx2, ty2, ta);
                bool take1 = iou1 > iou2;
                float best_iou = take1 ? iou1 : iou2;
                float bx = take1 ? pv[0] : pv[5];
                float by = take1 ? pv[1] : pv[6];
                float bw = take1 ? pv[2] : pv[7];
                float bh = take1 ? pv[3] : pv[8];
                float bc = take1 ? pv[4] : pv[9];
                float dx = bx - tb.x, dy = by - tb.y;
                float dwv = sqrtf(bw) - sqrtf(tb.z);
                float dhv = sqrtf(bh) - sqrtf(tb.w);
                reg += L_COORD * (dx * dx + dy * dy + dwv * dwv + dhv * dhv);
                float dc = bc - best_iou;
                contain += dc * dc;
            }
        }
    }

    // ---- One reduction per block (4 warps) ----
    #pragma unroll
    for (int off = 16; off > 0; off >>= 1) {
        reg     += __shfl_down_sync(0xFFFFFFFFu, reg, off);
        contain += __shfl_down_sync(0xFFFFFFFFu, contain, off);
        noobj   += __shfl_down_sync(0xFFFFFFFFu, noobj, off);
        cls     += __shfl_down_sync(0xFFFFFFFFu, cls, off);
    }

    if (lane == 0) {
        s_red[warp][0] = reg;
        s_red[warp][1] = contain;
        s_red[warp][2] = noobj;
        s_red[warp][3] = cls;
    }
    __syncthreads();

    if (warp == 0) {
        int comp = lane >> 2;     // 0..3 (lanes 0..15)
        int w    = lane & 3;      // 0..3
        float v = (lane < 16) ? s_red[w][comp] : 0.0f;
        v += __shfl_down_sync(0xFFFFFFFFu, v, 2);
        v += __shfl_down_sync(0xFFFFFFFFu, v, 1);
        if (lane < 16 && w == 0) atomicAdd(&g_acc[comp], v);
        __syncwarp();
        if (lane == 0) {
            __threadfence();
            unsigned int done = atomicAdd(&g_block_count, 1u);
            s_is_last = (done == gridDim.x - 1);
        }
    }
    __syncthreads();

    if (s_is_last && tid == 0) {
        float r  = g_acc[0];
        float ct = g_acc[1];
        float no = g_acc[2];
        float cl = g_acc[3];
        float total = r + ct + no + cl;
        out[0] = total * inv_n;
        out[1] = r  * inv_n;
        out[2] = ct * inv_n;
        out[3] = no * inv_n;
        out[4] = cl * inv_n;
        g_acc[0] = 0.0f; g_acc[1] = 0.0f; g_acc[2] = 0.0f; g_acc[3] = 0.0f;
        g_block_count = 0u;
        __threadfence();
    }
}

extern "C" void kernel_launch(void* const* d_in, const int* in_sizes, int n_in,
                              void* d_out, int out_size) {
    const float* pred = (const float*)d_in[0];
    const float* tbox = (const float*)d_in[1];
    const float* tcls = (const float*)d_in[2];
    const unsigned int* objmap = (const unsigned int*)d_in[3];

    int ncells = in_sizes[1] / 4;             // target_boxes has 4 per cell
    int n_imgs = ncells / (S_GRID * S_GRID);  // 4096
    int ntiles_full = ncells / WTILE;         // 25088 (exact)

    int dev = 0, sms = 148;
    cudaGetDevice(&dev);
    cudaDeviceGetAttribute(&sms, cudaDevAttrMultiProcessorCount, dev);
    int blocks = sms * 4;                     // 4 blocks/SM (46KB smem each)
    int max_blocks = (ntiles_full + WARPS - 1) / WARPS;
    if (blocks > max_blocks && max_blocks > 0) blocks = max_blocks;
    if (blocks < 1) blocks = 1;
    int nwarps_total = blocks * WARPS;

    yolo_tma_kernel<<<blocks, TPB>>>(pred, tbox, tcls, objmap,
                                     (float*)d_out, ncells, ntiles_full,
                                     nwarps_total, 1.0f / (float)n_imgs);
}

// round 17
// speedup vs baseline: 1.1263x; 1.1170x over previous
#include <cuda_runtime.h>
#include <cuda_bf16.h>
#include <cuda_pipeline_primitives.h>

#define S_GRID 14
#define INV_S (1.0f / 14.0f)
#define L_COORD 5.0f
#define L_NOOBJ 0.5f
#define TPB 128                  // threads per block
#define WARPS 4                  // warps per block
#define WTILE 32                 // cells per warp-tile
#define TILE_F (WTILE * 30)      // 960 floats per tile
#define TILE_F4 (TILE_F / 4)     // 240 float4 per tile

// Accumulators: [0]=reg, [1]=contain, [2]=noobj, [3]=cls
__device__ float g_acc[4];
__device__ unsigned int g_block_count;

__device__ __forceinline__ float iou_vs_tgt(float x, float y, float w, float h,
                                            float tx1, float ty1, float tx2, float ty2,
                                            float ta) {
    float cx = x * INV_S;
    float cy = y * INV_S;
    float x1 = cx - 0.5f * w, y1 = cy - 0.5f * h;
    float x2 = cx + 0.5f * w, y2 = cy + 0.5f * h;
    float lx = fmaxf(x1, tx1), ly = fmaxf(y1, ty1);
    float rx = fminf(x2, tx2), ry = fminf(y2, ty2);
    float iw = fmaxf(rx - lx, 0.0f), ih = fmaxf(ry - ly, 0.0f);
    float inter = iw * ih;
    float a1 = (x2 - x1) * (y2 - y1);
    return inter / (a1 + ta - inter);
}

// Stage one warp-tile (32 cells x 30 floats) via cp.async. Lane-strided.
__device__ __forceinline__ void stage_warp_tile(
    float* __restrict__ sbuf, const float* __restrict__ pred,
    int tile, int lane) {
    const float4* src4 = reinterpret_cast<const float4*>(pred + (size_t)tile * TILE_F);
    float4* dst4 = reinterpret_cast<float4*>(sbuf);
    #pragma unroll
    for (int k = 0; k < 8; k++) {
        int f4 = lane + k * 32;
        if (f4 < TILE_F4)
            __pipeline_memcpy_async(&dst4[f4], &src4[f4], 16);
    }
}

__global__ void __launch_bounds__(TPB, 5) yolo_pipe_kernel(
    const float* __restrict__ pred,            // [ncells, 30]
    const float* __restrict__ tbox,            // [ncells, 4]
    const float* __restrict__ tcls,            // [ncells, 20]
    const unsigned int* __restrict__ objmap,   // [ncells] bool widened to 4B
    float* __restrict__ out,
    int ncells, int ntiles, int nwarps_total, float inv_n) {

    __shared__ float s_pred[2][WARPS][TILE_F];   // 30.7 KB
    __shared__ float s_red[WARPS][4];
    __shared__ bool s_is_last;

    int tid  = threadIdx.x;
    int lane = tid & 31;
    int warp = tid >> 5;
    int gwarp = blockIdx.x * WARPS + warp;

    float reg = 0.0f, contain = 0.0f, noobj = 0.0f, cls = 0.0f;

    int stride = nwarps_total;
    int tile = gwarp;
    int b = 0;

    if (tile < ntiles) {
        // ---------- Prologue ----------
        // Flags for tile0 and tile0+stride.
        unsigned int fA = objmap[tile * WTILE + lane];
        unsigned int fB = (tile + stride < ntiles)
                        ? objmap[(tile + stride) * WTILE + lane] : 0u;

        // Gathers for tile0 (cold start, unavoidable demand latency once).
        float4 tbC = make_float4(0.f,0.f,0.f,0.f);
        float4 tcC0, tcC1, tcC2, tcC3, tcC4;
        tcC0 = tcC1 = tcC2 = tcC3 = tcC4 = make_float4(0.f,0.f,0.f,0.f);
        if (fA != 0u) {
            int i0 = tile * WTILE + lane;
            tbC = __ldg(reinterpret_cast<const float4*>(tbox + (size_t)i0 * 4));
            const float4* tc4 = reinterpret_cast<const float4*>(tcls + (size_t)i0 * 20);
            tcC0 = __ldg(tc4 + 0); tcC1 = __ldg(tc4 + 1); tcC2 = __ldg(tc4 + 2);
            tcC3 = __ldg(tc4 + 3); tcC4 = __ldg(tc4 + 4);
        }

        // Stage pred for tile0 (group 1).
        stage_warp_tile(&s_pred[0][warp][0], pred, tile, lane);
        __pipeline_commit();

        // ---------- Main loop ----------
        for (; tile < ntiles; tile += stride) {
            int t_nx  = tile + stride;        // next tile (gathers prefetch)
            int t_nx2 = tile + 2 * stride;    // next-next (flag prefetch)

            // 1) Gathers for NEXT tile, issued a full iteration before use.
            float4 tbN = make_float4(0.f,0.f,0.f,0.f);
            float4 tcN0, tcN1, tcN2, tcN3, tcN4;
            tcN0 = tcN1 = tcN2 = tcN3 = tcN4 = make_float4(0.f,0.f,0.f,0.f);
            if (fB != 0u) {
                int inx = t_nx * WTILE + lane;
                tbN = __ldg(reinterpret_cast<const float4*>(tbox + (size_t)inx * 4));
                const float4* tc4 = reinterpret_cast<const float4*>(tcls + (size_t)inx * 20);
                tcN0 = __ldg(tc4 + 0); tcN1 = __ldg(tc4 + 1); tcN2 = __ldg(tc4 + 2);
                tcN3 = __ldg(tc4 + 3); tcN4 = __ldg(tc4 + 4);
            }

            // 2) Stage pred for next tile.
            bool have_next = (t_nx < ntiles);
            if (have_next) {
                stage_warp_tile(&s_pred[b ^ 1][warp][0], pred, t_nx, lane);
                __pipeline_commit();
            }

            // 3) Flag for tile+2*stride (consumed two iterations later).
            unsigned int fC = (t_nx2 < ntiles)
                            ? __ldg(objmap + t_nx2 * WTILE + lane) : 0u;

            // 4) Wait for THIS tile's pred.
            if (have_next) __pipeline_wait_prior(1);
            else           __pipeline_wait_prior(0);
            __syncwarp();

            // 5) Compute tile using fully-landed data.
            const float* pv = &s_pred[b][warp][0] + lane * 30;
            if (fA == 0u) {
                float c1 = pv[4], c2 = pv[9];
                noobj += L_NOOBJ * (c1 * c1 + c2 * c2);
            } else {
                float csum = 0.0f;
                {
                    float d0 = pv[10] - tcC0.x, d1 = pv[11] - tcC0.y,
                          d2 = pv[12] - tcC0.z, d3 = pv[13] - tcC0.w;
                    csum += d0*d0 + d1*d1 + d2*d2 + d3*d3;
                    d0 = pv[14] - tcC1.x; d1 = pv[15] - tcC1.y;
                    d2 = pv[16] - tcC1.z; d3 = pv[17] - tcC1.w;
                    csum += d0*d0 + d1*d1 + d2*d2 + d3*d3;
                    d0 = pv[18] - tcC2.x; d1 = pv[19] - tcC2.y;
                    d2 = pv[20] - tcC2.z; d3 = pv[21] - tcC2.w;
                    csum += d0*d0 + d1*d1 + d2*d2 + d3*d3;
                    d0 = pv[22] - tcC3.x; d1 = pv[23] - tcC3.y;
                    d2 = pv[24] - tcC3.z; d3 = pv[25] - tcC3.w;
                    csum += d0*d0 + d1*d1 + d2*d2 + d3*d3;
                    d0 = pv[26] - tcC4.x; d1 = pv[27] - tcC4.y;
                    d2 = pv[28] - tcC4.z; d3 = pv[29] - tcC4.w;
                    csum += d0*d0 + d1*d1 + d2*d2 + d3*d3;
                }
                cls += csum;

                float tcx = tbC.x * INV_S, tcy = tbC.y * INV_S;
                float tx1 = tcx - 0.5f * tbC.z, ty1 = tcy - 0.5f * tbC.w;
                float tx2 = tcx + 0.5f * tbC.z, ty2 = tcy + 0.5f * tbC.w;
                float ta = (tx2 - tx1) * (ty2 - ty1);

                float iou1 = iou_vs_tgt(pv[0], pv[1], pv[2], pv[3], tx1, ty1, tx2, ty2, ta);
                float iou2 = iou_vs_tgt(pv[5], pv[6], pv[7], pv[8], tx1, ty1, tx2, ty2, ta);

                bool take1 = iou1 > iou2;
                float best_iou = take1 ? iou1 : iou2;
                float bx = take1 ? pv[0] : pv[5];
                float by = take1 ? pv[1] : pv[6];
                float bw = take1 ? pv[2] : pv[7];
                float bh = take1 ? pv[3] : pv[8];
                float bc = take1 ? pv[4] : pv[9];

                float dx = bx - tbC.x, dy = by - tbC.y;
                float xy_err = dx * dx + dy * dy;
                float dw = sqrtf(bw) - sqrtf(tbC.z);
                float dh = sqrtf(bh) - sqrtf(tbC.w);
                float wh_err = dw * dw + dh * dh;
                reg += L_COORD * (xy_err + wh_err);

                float dc = bc - best_iou;
                contain += dc * dc;
            }
            __syncwarp();    // warp done with buffer b before reuse

            // 6) Rotate pipeline registers.
            fA = fB; fB = fC;
            tbC = tbN;
            tcC0 = tcN0; tcC1 = tcN1; tcC2 = tcN2; tcC3 = tcN3; tcC4 = tcN4;
            b ^= 1;
        }
    }

    // Remainder cells (ncells % WTILE, normally 0).
    if (blockIdx.x == 0 && warp == 0) {
        int tail_start = (ncells / WTILE) * WTILE;
        for (int i = tail_start + lane; i < ncells; i += 32) {
            unsigned int flag = objmap[i];
            const float* p = pred + (size_t)i * 30;
            if (flag == 0u) {
                float c1 = __ldg(p + 4), c2 = __ldg(p + 9);
                noobj += L_NOOBJ * (c1 * c1 + c2 * c2);
            } else {
                float pv[30];
                #pragma unroll
                for (int j = 0; j < 15; j++) {
                    float2 v = __ldg(reinterpret_cast<const float2*>(p + 2 * j));
                    pv[2 * j] = v.x; pv[2 * j + 1] = v.y;
                }
                float4 tb = __ldg(reinterpret_cast<const float4*>(tbox + (size_t)i * 4));
                const float4* tc4 = reinterpret_cast<const float4*>(tcls + (size_t)i * 20);
                float csum = 0.0f;
                #pragma unroll
                for (int j = 0; j < 5; j++) {
                    float4 t = __ldg(tc4 + j);
                    float d0 = pv[10 + 4*j + 0] - t.x;
                    float d1 = pv[10 + 4*j + 1] - t.y;
                    float d2 = pv[10 + 4*j + 2] - t.z;
                    float d3 = pv[10 + 4*j + 3] - t.w;
                    csum += d0*d0 + d1*d1 + d2*d2 + d3*d3;
                }
                cls += csum;
                float tcx = tb.x * INV_S, tcy = tb.y * INV_S;
                float tx1 = tcx - 0.5f * tb.z, ty1 = tcy - 0.5f * tb.w;
                float tx2 = tcx + 0.5f * tb.z, ty2 = tcy + 0.5f * tb.w;
                float ta = (tx2 - tx1) * (ty2 - ty1);
                float iou1 = iou_vs_tgt(pv[0], pv[1], pv[2], pv[3], tx1, ty1, tx2, ty2, ta);
                float iou2 = iou_vs_tgt(pv[5], pv[6], pv[7], pv[8], tx1, ty1, tx2, ty2, ta);
                bool take1 = iou1 > iou2;
                float best_iou = take1 ? iou1 : iou2;
                float bx = take1 ? pv[0] : pv[5];
                float by = take1 ? pv[1] : pv[6];
                float bw = take1 ? pv[2] : pv[7];
                float bh = take1 ? pv[3] : pv[8];
                float bc = take1 ? pv[4] : pv[9];
                float dx = bx - tb.x, dy = by - tb.y;
                float dwv = sqrtf(bw) - sqrtf(tb.z);
                float dhv = sqrtf(bh) - sqrtf(tb.w);
                reg += L_COORD * (dx*dx + dy*dy + dwv*dwv + dhv*dhv);
                float dc = bc - best_iou;
                contain += dc * dc;
            }
        }
    }

    // ---- One reduction per block ----
    #pragma unroll
    for (int off = 16; off > 0; off >>= 1) {
        reg     += __shfl_down_sync(0xFFFFFFFFu, reg, off);
        contain += __shfl_down_sync(0xFFFFFFFFu, contain, off);
        noobj   += __shfl_down_sync(0xFFFFFFFFu, noobj, off);
        cls     += __shfl_down_sync(0xFFFFFFFFu, cls, off);
    }

    if (lane == 0) {
        s_red[warp][0] = reg;
        s_red[warp][1] = contain;
        s_red[warp][2] = noobj;
        s_red[warp][3] = cls;
    }
    __syncthreads();

    if (warp == 0) {
        int comp = lane >> 2;     // 0..3 (lanes 0..15)
        int w    = lane & 3;      // 0..3
        float v = (lane < 16) ? s_red[w][comp] : 0.0f;
        v += __shfl_down_sync(0xFFFFFFFFu, v, 2);
        v += __shfl_down_sync(0xFFFFFFFFu, v, 1);
        if (lane < 16 && w == 0) atomicAdd(&g_acc[comp], v);
        __syncwarp();
        if (lane == 0) {
            __threadfence();
            unsigned int done = atomicAdd(&g_block_count, 1u);
            s_is_last = (done == gridDim.x - 1);
        }
    }
    __syncthreads();

    if (s_is_last && tid == 0) {
        float r  = g_acc[0];
        float ct = g_acc[1];
        float no = g_acc[2];
        float cl = g_acc[3];
        float total = r + ct + no + cl;
        out[0] = total * inv_n;
        out[1] = r  * inv_n;
        out[2] = ct * inv_n;
        out[3] = no * inv_n;
        out[4] = cl * inv_n;
        g_acc[0] = 0.0f; g_acc[1] = 0.0f; g_acc[2] = 0.0f; g_acc[3] = 0.0f;
        g_block_count = 0u;
        __threadfence();
    }
}

extern "C" void kernel_launch(void* const* d_in, const int* in_sizes, int n_in,
                              void* d_out, int out_size) {
    const float* pred = (const float*)d_in[0];
    const float* tbox = (const float*)d_in[1];
    const float* tcls = (const float*)d_in[2];
    const unsigned int* objmap = (const unsigned int*)d_in[3];

    int ncells = in_sizes[1] / 4;             // target_boxes has 4 per cell
    int n_imgs = ncells / (S_GRID * S_GRID);  // 4096
    int ntiles = ncells / WTILE;              // 25088 (exact)

    int dev = 0, sms = 148;
    cudaGetDevice(&dev);
    cudaDeviceGetAttribute(&sms, cudaDevAttrMultiProcessorCount, dev);
    int blocks = sms * 5;                     // 5 blocks/SM (regs/smem capped)
    int max_blocks = (ntiles + WARPS - 1) / WARPS;
    if (blocks > max_blocks && max_blocks > 0) blocks = max_blocks;
    if (blocks < 1) blocks = 1;
    int nwarps_total = blocks * WARPS;

    yolo_pipe_kernel<<<blocks, TPB>>>(pred, tbox, tcls, objmap,
                                      (float*)d_out, ncells, ntiles,
                                      nwarps_total, 1.0f / (float)n_imgs);
}